// round 1
// baseline (speedup 1.0000x reference)
#include <cuda_runtime.h>
#include <cuda_bf16.h>
#include <cstdint>

// ---------------------------------------------------------------------------
// DeepFM forward, fp32 baseline.
//   B=16384, F=26 fields, D=32 embed, DIN=832, H1=256, H2=128, V=100000
// Pipeline (6 launches, graph-capturable, no allocations):
//   0) zero_stats
//   1) gather_fm  : embedding gather -> X (B x 832), FM logit (+bias) -> g_fm
//   2) sgemm<832,256,false> : H1pre = X @ W1 + b1
//   3) col_stats(H1pre, 256)
//   4) sgemm<256,128,true>  : H2pre = relu(BN(H1pre)) @ W2 + b2  (BN fused in A load)
//   5) col_stats(H2pre, 128)
//   6) final_k    : out = g_fm + relu(BN(H2pre)) @ W3 + b3
// SGEMM inner loop uses packed fma.rn.f32x2 (2 FMA/instr on Blackwell fp32 pipe).
// ---------------------------------------------------------------------------

#define BATCH  16384
#define NF     26
#define ED     32
#define DIN    832      // 26*32
#define H1N    256
#define H2N    128
#define VOCAB  100000
#define BN_EPS 1e-5f

// scratch (static device allocations are allowed)
__device__ float g_X [(size_t)BATCH * DIN];     // 54.5 MB
__device__ float g_H1[(size_t)BATCH * H1N];     // 16.8 MB
__device__ float g_H2[(size_t)BATCH * H2N];     //  8.4 MB
__device__ float g_fm[BATCH];
__device__ float g_stats1[2 * H1N];             // colsum, colsumsq of H1pre
__device__ float g_stats2[2 * H2N];             // colsum, colsumsq of H2pre

// ---- packed f32x2 helpers --------------------------------------------------
__device__ __forceinline__ unsigned long long bcast2(float a) {
    unsigned long long r;
    asm("mov.b64 %0, {%1, %1};" : "=l"(r) : "f"(a));
    return r;
}
__device__ __forceinline__ void fma2(unsigned long long& d, unsigned long long a,
                                     unsigned long long b) {
    asm("fma.rn.f32x2 %0, %1, %2, %0;" : "+l"(d) : "l"(a), "l"(b));
}
__device__ __forceinline__ float2 unpack2(unsigned long long v) {
    float2 r;
    asm("mov.b64 {%0, %1}, %2;" : "=f"(r.x), "=f"(r.y) : "l"(v));
    return r;
}

// ---- 0) zero the stats accumulators ---------------------------------------
__global__ void zero_stats_k() {
    int t = threadIdx.x;                 // 256 threads
    g_stats1[t] = 0.f;
    g_stats1[H1N + t] = 0.f;
    if (t < H2N) { g_stats2[t] = 0.f; g_stats2[H2N + t] = 0.f; }
}

// ---- 1) embedding gather + FM ----------------------------------------------
// one warp per batch row; lane = embedding dim
__global__ void gather_fm_k(const int* __restrict__ xc,
                            const float* __restrict__ lin_tab,
                            const float* __restrict__ lat_tab,
                            const float* __restrict__ bias) {
    int row  = blockIdx.x * (blockDim.x >> 5) + (threadIdx.x >> 5);
    int lane = threadIdx.x & 31;
    if (row >= BATCH) return;

    int   idx  = 0;
    float linv = 0.f;
    if (lane < NF) {
        idx  = xc[row * NF + lane];
        linv = lin_tab[lane * VOCAB + idx];
    }

    float sdim = 0.f;   // per-dim sum over fields
    float sq   = 0.f;   // per-dim sum of squares over fields
    float* xrow = &g_X[(size_t)row * DIN];
#pragma unroll
    for (int f = 0; f < NF; ++f) {
        int id = __shfl_sync(0xffffffffu, idx, f);
        float e = lat_tab[((size_t)f * VOCAB + id) * ED + lane];
        xrow[f * ED + lane] = e;
        sdim += e;
        sq   += e * e;
    }
    float t = sdim * sdim - sq;
#pragma unroll
    for (int o = 16; o; o >>= 1) {
        t    += __shfl_xor_sync(0xffffffffu, t, o);
        linv += __shfl_xor_sync(0xffffffffu, linv, o);
    }
    if (lane == 0) g_fm[row] = linv + 0.5f * t + bias[0];
}

// ---- SGEMM: C(BATCH x NCOLS) = op(A)(BATCH x KTOT) @ Bm(KTOT x NCOLS) + bvec
// 128x128 block tile, 8x8 per thread, KT=8, f32x2 inner loop.
// If BN: A element (r,k) -> relu(a*scale[k]+shift[k]) with batch stats.
template<int KTOT, int NCOLS, bool BN>
__global__ __launch_bounds__(256, 2)
void sgemm_k(const float* __restrict__ A, const float* __restrict__ Bm,
             const float* __restrict__ bvec,
             const float* __restrict__ gvec, const float* __restrict__ bevec,
             const float* __restrict__ stats,
             float* __restrict__ C) {
    __shared__ __align__(16) float As[8][128];
    __shared__ __align__(16) float Bs[8][128];
    __shared__ float sc[BN ? KTOT : 1];
    __shared__ float sh[BN ? KTOT : 1];

    const int tid = threadIdx.x;
    if (BN) {  // only instantiated with KTOT == blockDim == 256
        float s  = stats[tid];
        float sq = stats[KTOT + tid];
        float mean = s * (1.f / BATCH);
        float var  = sq * (1.f / BATCH) - mean * mean;
        float rstd = rsqrtf(var + BN_EPS);
        float scl  = gvec[tid] * rstd;
        sc[tid] = scl;
        sh[tid] = bevec[tid] - mean * scl;
        __syncthreads();
    }

    const int rowBase = blockIdx.y * 128;
    const int colBase = blockIdx.x * 128;
    const int rowA = tid >> 1, kA  = (tid & 1) * 4;
    const int rowB = tid >> 5, colB = (tid & 31) * 4;
    const int ty = tid >> 4, tx = tid & 15;

    unsigned long long acc[8][4];
#pragma unroll
    for (int i = 0; i < 8; ++i)
#pragma unroll
        for (int j = 0; j < 4; ++j) acc[i][j] = 0ull;

    for (int kt = 0; kt < KTOT; kt += 8) {
        float4 av = *(const float4*)&A[(size_t)(rowBase + rowA) * KTOT + kt + kA];
        float4 bv = *(const float4*)&Bm[(size_t)(kt + rowB) * NCOLS + colBase + colB];
        if (BN) {
            const float* scp = &sc[kt + kA];
            const float* shp = &sh[kt + kA];
            av.x = fmaxf(fmaf(av.x, scp[0], shp[0]), 0.f);
            av.y = fmaxf(fmaf(av.y, scp[1], shp[1]), 0.f);
            av.z = fmaxf(fmaf(av.z, scp[2], shp[2]), 0.f);
            av.w = fmaxf(fmaf(av.w, scp[3], shp[3]), 0.f);
        }
        __syncthreads();
        As[kA + 0][rowA] = av.x;
        As[kA + 1][rowA] = av.y;
        As[kA + 2][rowA] = av.z;
        As[kA + 3][rowA] = av.w;
        *(float4*)&Bs[rowB][colB] = bv;
        __syncthreads();

#pragma unroll
        for (int kk = 0; kk < 8; ++kk) {
            float4 a0 = *(const float4*)&As[kk][ty * 8];
            float4 a1 = *(const float4*)&As[kk][ty * 8 + 4];
            ulonglong2 b0 = *(const ulonglong2*)&Bs[kk][tx * 8];
            ulonglong2 b1 = *(const ulonglong2*)&Bs[kk][tx * 8 + 4];
            float a[8] = {a0.x, a0.y, a0.z, a0.w, a1.x, a1.y, a1.z, a1.w};
#pragma unroll
            for (int i = 0; i < 8; ++i) {
                unsigned long long ab = bcast2(a[i]);
                fma2(acc[i][0], ab, b0.x);
                fma2(acc[i][1], ab, b0.y);
                fma2(acc[i][2], ab, b1.x);
                fma2(acc[i][3], ab, b1.y);
            }
        }
    }

#pragma unroll
    for (int i = 0; i < 8; ++i) {
        int r = rowBase + ty * 8 + i;
        int c = colBase + tx * 8;
        float2 p0 = unpack2(acc[i][0]);
        float2 p1 = unpack2(acc[i][1]);
        float2 p2 = unpack2(acc[i][2]);
        float2 p3 = unpack2(acc[i][3]);
        float4 o0 = {p0.x + bvec[c + 0], p0.y + bvec[c + 1],
                     p1.x + bvec[c + 2], p1.y + bvec[c + 3]};
        float4 o1 = {p2.x + bvec[c + 4], p2.y + bvec[c + 5],
                     p3.x + bvec[c + 6], p3.y + bvec[c + 7]};
        *(float4*)&C[(size_t)r * NCOLS + c]     = o0;
        *(float4*)&C[(size_t)r * NCOLS + c + 4] = o1;
    }
}

// ---- column sum / sumsq (blockDim == ncols) --------------------------------
__global__ void col_stats_k(const float* __restrict__ H, float* __restrict__ stats,
                            int ncols) {
    int c = threadIdx.x;
    int rowsPer = BATCH / gridDim.x;
    int r0 = blockIdx.x * rowsPer;
    float s = 0.f, sq = 0.f;
    for (int r = r0; r < r0 + rowsPer; ++r) {
        float v = H[(size_t)r * ncols + c];
        s  += v;
        sq += v * v;
    }
    atomicAdd(&stats[c], s);
    atomicAdd(&stats[ncols + c], sq);
}

// ---- final: out = fm + relu(BN(H2pre)) @ W3 + b3 ---------------------------
__global__ void final_k(const float* __restrict__ W3, const float* __restrict__ b3,
                        const float* __restrict__ g2, const float* __restrict__ be2,
                        float* __restrict__ out) {
    __shared__ float sc[H2N], sh[H2N], w3s[H2N];
    int tid = threadIdx.x;  // 256 threads, 8 warps
    if (tid < H2N) {
        float s  = g_stats2[tid];
        float sq = g_stats2[H2N + tid];
        float mean = s * (1.f / BATCH);
        float var  = sq * (1.f / BATCH) - mean * mean;
        float rstd = rsqrtf(var + BN_EPS);
        float scl  = g2[tid] * rstd;
        sc[tid] = scl;
        sh[tid] = be2[tid] - mean * scl;
        w3s[tid] = W3[tid];
    }
    __syncthreads();
    int warp = tid >> 5, lane = tid & 31;
    int row = blockIdx.x * 8 + warp;
    float acc = 0.f;
#pragma unroll
    for (int j = 0; j < 4; ++j) {
        int c = lane + j * 32;
        float v = g_H2[(size_t)row * H2N + c];
        float h = fmaxf(fmaf(v, sc[c], sh[c]), 0.f);
        acc += h * w3s[c];
    }
#pragma unroll
    for (int o = 16; o; o >>= 1) acc += __shfl_xor_sync(0xffffffffu, acc, o);
    if (lane == 0) out[row] = g_fm[row] + acc + b3[0];
}

// ---------------------------------------------------------------------------
extern "C" void kernel_launch(void* const* d_in, const int* in_sizes, int n_in,
                              void* d_out, int out_size) {
    const int*   xc   = (const int*)  d_in[0];
    const float* lin  = (const float*)d_in[1];
    const float* lat  = (const float*)d_in[2];
    const float* W1   = (const float*)d_in[3];
    const float* b1   = (const float*)d_in[4];
    const float* g1   = (const float*)d_in[5];
    const float* be1  = (const float*)d_in[6];
    const float* W2   = (const float*)d_in[7];
    const float* b2   = (const float*)d_in[8];
    const float* g2   = (const float*)d_in[9];
    const float* be2  = (const float*)d_in[10];
    const float* W3   = (const float*)d_in[11];
    const float* b3   = (const float*)d_in[12];
    const float* bias = (const float*)d_in[13];
    float* out = (float*)d_out;

    float* pX  = nullptr; cudaGetSymbolAddress((void**)&pX,  g_X);
    float* pH1 = nullptr; cudaGetSymbolAddress((void**)&pH1, g_H1);
    float* pH2 = nullptr; cudaGetSymbolAddress((void**)&pH2, g_H2);
    float* pS1 = nullptr; cudaGetSymbolAddress((void**)&pS1, g_stats1);
    float* pS2 = nullptr; cudaGetSymbolAddress((void**)&pS2, g_stats2);

    zero_stats_k<<<1, 256>>>();
    gather_fm_k<<<BATCH / 8, 256>>>(xc, lin, lat, bias);
    sgemm_k<DIN, H1N, false><<<dim3(H1N / 128, BATCH / 128), 256>>>(
        pX, W1, b1, nullptr, nullptr, nullptr, pH1);
    col_stats_k<<<128, H1N>>>(pH1, pS1, H1N);
    sgemm_k<H1N, H2N, true><<<dim3(H2N / 128, BATCH / 128), 256>>>(
        pH1, W2, b2, g1, be1, pS1, pH2);
    col_stats_k<<<128, H2N>>>(pH2, pS2, H2N);
    final_k<<<BATCH / 8, 256>>>(W3, b3, g2, be2, out);
}

// round 4
// speedup vs baseline: 2.9339x; 2.9339x over previous
#include <cuda_runtime.h>
#include <cuda_bf16.h>
#include <cstdint>

// ---------------------------------------------------------------------------
// DeepFM forward — HMMA (mma.sync bf16) GEMMs, bf16 hi/lo 3-term split.
//   B=16384, F=26, D=32, DIN=832, H1=256, H2=128, V=100000
// Pipeline:
//   zero_stats; prep_w (W -> k-major bf16 hi/lo); gather_fm (X bf16 hi/lo +
//   FM logit); gemm_mma<832,256>; col_stats; bn_prep; act (BN+ReLU bf16);
//   gemm_mma<256,128>; col_stats; final.
// GEMM: 128x128 CTA tile, 8 warps (4m x 2n), warp tile 32x64, k-chunk 64,
// cp.async single-buffer SMEM (72KB), 2 CTAs/SM for load/compute overlap.
// ---------------------------------------------------------------------------

#define BATCH  16384
#define NF     26
#define ED     32
#define DIN    832
#define H1N    256
#define H2N    128
#define VOCAB  100000
#define BN_EPS 1e-5f

// ---- scratch ---------------------------------------------------------------
__device__ unsigned short g_Xh[(size_t)BATCH * DIN];
__device__ unsigned short g_Xl[(size_t)BATCH * DIN];
__device__ float          g_H1[(size_t)BATCH * H1N];
__device__ unsigned short g_A2h[(size_t)BATCH * H1N];
__device__ unsigned short g_A2l[(size_t)BATCH * H1N];
__device__ float          g_H2[(size_t)BATCH * H2N];
__device__ unsigned short g_W1Th[H1N * DIN], g_W1Tl[H1N * DIN];
__device__ unsigned short g_W2Th[H2N * H1N], g_W2Tl[H2N * H1N];
__device__ float g_fm[BATCH];
__device__ float g_stats1[2 * H1N];
__device__ float g_stats2[2 * H2N];
__device__ float g_sc1[H1N], g_sh1[H1N];

// ---- PTX helpers (all plain-sm_103-legal: sm_80 era) -----------------------
__device__ __forceinline__ uint32_t smem_u32(const void* p) {
    uint32_t a;
    asm("{ .reg .u64 t; cvta.to.shared.u64 t, %1; cvt.u32.u64 %0, t; }"
        : "=r"(a) : "l"(p));
    return a;
}
__device__ __forceinline__ void cp16(uint32_t dst, const void* src) {
    asm volatile("cp.async.cg.shared.global [%0], [%1], 16;"
                 :: "r"(dst), "l"(src));
}
#define CP_COMMIT() asm volatile("cp.async.commit_group;" ::: "memory")
#define CP_WAIT0()  asm volatile("cp.async.wait_group 0;" ::: "memory")

__device__ __forceinline__ void ldsm4(uint32_t* r, uint32_t addr) {
    asm volatile("ldmatrix.sync.aligned.m8n8.x4.shared.b16 {%0,%1,%2,%3}, [%4];"
                 : "=r"(r[0]), "=r"(r[1]), "=r"(r[2]), "=r"(r[3]) : "r"(addr));
}
__device__ __forceinline__ void mma16816(float* d, const uint32_t* a,
                                         const uint32_t* b) {
    asm volatile(
        "mma.sync.aligned.m16n8k16.row.col.f32.bf16.bf16.f32 "
        "{%0,%1,%2,%3}, {%4,%5,%6,%7}, {%8,%9}, {%0,%1,%2,%3};"
        : "+f"(d[0]), "+f"(d[1]), "+f"(d[2]), "+f"(d[3])
        : "r"(a[0]), "r"(a[1]), "r"(a[2]), "r"(a[3]), "r"(b[0]), "r"(b[1]));
}

// ---- tiny kernels ----------------------------------------------------------
__global__ void zero_stats_k() {
    int t = threadIdx.x;
    g_stats1[t] = 0.f; g_stats1[H1N + t] = 0.f;
    if (t < H2N) { g_stats2[t] = 0.f; g_stats2[H2N + t] = 0.f; }
}

__global__ void prep_w_k(const float* __restrict__ W1, const float* __restrict__ W2) {
    const int t1 = DIN * H1N;
    const int tot = t1 + H1N * H2N;
    for (int i = blockIdx.x * blockDim.x + threadIdx.x; i < tot;
         i += gridDim.x * blockDim.x) {
        if (i < t1) {
            int k = i / H1N, n = i % H1N;
            float v = W1[i];
            __nv_bfloat16 h = __float2bfloat16(v);
            __nv_bfloat16 l = __float2bfloat16(v - __bfloat162float(h));
            g_W1Th[n * DIN + k] = __bfloat16_as_ushort(h);
            g_W1Tl[n * DIN + k] = __bfloat16_as_ushort(l);
        } else {
            int j = i - t1;
            int k = j / H2N, n = j % H2N;
            float v = W2[j];
            __nv_bfloat16 h = __float2bfloat16(v);
            __nv_bfloat16 l = __float2bfloat16(v - __bfloat162float(h));
            g_W2Th[n * H1N + k] = __bfloat16_as_ushort(h);
            g_W2Tl[n * H1N + k] = __bfloat16_as_ushort(l);
        }
    }
}

// one warp per row: gather embeddings, FM logit, bf16 hi/lo X
__global__ void gather_fm_k(const int* __restrict__ xc,
                            const float* __restrict__ lin_tab,
                            const float* __restrict__ lat_tab,
                            const float* __restrict__ bias) {
    int row  = blockIdx.x * 8 + (threadIdx.x >> 5);
    int lane = threadIdx.x & 31;

    int   idx  = 0;
    float linv = 0.f;
    if (lane < NF) {
        idx  = xc[row * NF + lane];
        linv = lin_tab[lane * VOCAB + idx];
    }
    float sdim = 0.f, sq = 0.f;
    unsigned short* xh = &g_Xh[(size_t)row * DIN];
    unsigned short* xl = &g_Xl[(size_t)row * DIN];
#pragma unroll
    for (int f = 0; f < NF; ++f) {
        int id = __shfl_sync(0xffffffffu, idx, f);
        float e = lat_tab[((size_t)f * VOCAB + id) * ED + lane];
        __nv_bfloat16 h = __float2bfloat16(e);
        __nv_bfloat16 l = __float2bfloat16(e - __bfloat162float(h));
        xh[f * ED + lane] = __bfloat16_as_ushort(h);
        xl[f * ED + lane] = __bfloat16_as_ushort(l);
        sdim += e; sq += e * e;
    }
    float t = sdim * sdim - sq;
#pragma unroll
    for (int o = 16; o; o >>= 1) {
        t    += __shfl_xor_sync(0xffffffffu, t, o);
        linv += __shfl_xor_sync(0xffffffffu, linv, o);
    }
    if (lane == 0) g_fm[row] = linv + 0.5f * t + bias[0];
}

// ---- HMMA GEMM: C[B x NCOLS] = A[B x KTOT] @ Bt[NCOLS x KTOT]^T + bias ----
// SMEM layout (halves, row stride 72 = 64 data + 8 pad):
//   [0)      Ah 128x72
//   [9216)   Al 128x72
//   [18432)  Bh 128x72
//   [27648)  Bl 128x72     total 36864 halves = 73728 bytes
template<int KTOT, int NCOLS>
__global__ __launch_bounds__(256, 2)
void gemm_mma(const unsigned short* __restrict__ Ah,
              const unsigned short* __restrict__ Al,
              const unsigned short* __restrict__ Bh,
              const unsigned short* __restrict__ Bl,
              const float* __restrict__ bias, float* __restrict__ C) {
    extern __shared__ char smem[];
    constexpr int STR = 72;                    // halves per row
    constexpr int OFF_AH = 0;
    constexpr int OFF_AL = 128 * STR * 2;      // bytes
    constexpr int OFF_BH = 2 * 128 * STR * 2;
    constexpr int OFF_BL = 3 * 128 * STR * 2;
    constexpr int NCHUNK = KTOT / 64;

    const uint32_t sb = smem_u32(smem);
    const int tid = threadIdx.x;
    const int lane = tid & 31;
    const int wid = tid >> 5;
    const int warp_m = wid & 3;                // 0..3  -> m offset *32
    const int warp_n = wid >> 2;               // 0..1  -> n offset *64
    const int rowBase = blockIdx.x * 128;
    const int colBase = blockIdx.y * 128;

    float acc[2][8][4];
#pragma unroll
    for (int i = 0; i < 2; ++i)
#pragma unroll
        for (int j = 0; j < 8; ++j)
#pragma unroll
            for (int k = 0; k < 4; ++k) acc[i][j][k] = 0.f;

    // ldmatrix source addresses (fixed per thread, vary by ks offset)
    const int a_row = warp_m * 32 + (lane & 15);
    const int a_col8 = (lane >> 4) << 3;              // 0 or 8
    const int b_row_base = warp_n * 64 + (lane & 7) + ((lane >> 4) << 3);
    const int b_col8 = ((lane >> 3) & 1) << 3;        // 0 or 8

    for (int kc = 0; kc < NCHUNK; ++kc) {
        // ---- load chunk via cp.async ----
#pragma unroll
        for (int p = 0; p < 4; ++p) {
            int row = p * 32 + (tid >> 3);
            int seg = tid & 7;
            uint32_t soff = (uint32_t)(row * STR + seg * 8) * 2;
            size_t ga = (size_t)(rowBase + row) * KTOT + kc * 64 + seg * 8;
            size_t gb = (size_t)(colBase + row) * KTOT + kc * 64 + seg * 8;
            cp16(sb + OFF_AH + soff, Ah + ga);
            cp16(sb + OFF_AL + soff, Al + ga);
            cp16(sb + OFF_BH + soff, Bh + gb);
            cp16(sb + OFF_BL + soff, Bl + gb);
        }
        CP_COMMIT();
        CP_WAIT0();
        __syncthreads();

        // ---- compute: 4 k16 steps ----
#pragma unroll
        for (int ks = 0; ks < 4; ++ks) {
            uint32_t ah[2][4], al[2][4];
#pragma unroll
            for (int mt = 0; mt < 2; ++mt) {
                uint32_t off = (uint32_t)((a_row + mt * 16) * STR +
                                          ks * 16 + a_col8) * 2;
                ldsm4(ah[mt], sb + OFF_AH + off);
                ldsm4(al[mt], sb + OFF_AL + off);
            }
#pragma unroll
            for (int nb = 0; nb < 4; ++nb) {
                uint32_t bh[4], bl[4];
                uint32_t off = (uint32_t)((b_row_base + nb * 16) * STR +
                                          ks * 16 + b_col8) * 2;
                ldsm4(bh, sb + OFF_BH + off);
                ldsm4(bl, sb + OFF_BL + off);
#pragma unroll
                for (int mt = 0; mt < 2; ++mt) {
                    mma16816(acc[mt][2 * nb],     ah[mt], bh);
                    mma16816(acc[mt][2 * nb],     ah[mt], bl);
                    mma16816(acc[mt][2 * nb],     al[mt], bh);
                    mma16816(acc[mt][2 * nb + 1], ah[mt], bh + 2);
                    mma16816(acc[mt][2 * nb + 1], ah[mt], bl + 2);
                    mma16816(acc[mt][2 * nb + 1], al[mt], bh + 2);
                }
            }
        }
        __syncthreads();
    }

    // ---- epilogue: add bias, store ----
#pragma unroll
    for (int mt = 0; mt < 2; ++mt) {
        int r0 = rowBase + warp_m * 32 + mt * 16 + (lane >> 2);
#pragma unroll
        for (int nt = 0; nt < 8; ++nt) {
            int c = colBase + warp_n * 64 + nt * 8 + 2 * (lane & 3);
            float2 bv = *(const float2*)&bias[c];
            float2 v0 = {acc[mt][nt][0] + bv.x, acc[mt][nt][1] + bv.y};
            float2 v1 = {acc[mt][nt][2] + bv.x, acc[mt][nt][3] + bv.y};
            *(float2*)&C[(size_t)r0 * NCOLS + c]       = v0;
            *(float2*)&C[(size_t)(r0 + 8) * NCOLS + c] = v1;
        }
    }
}

// ---- column sum / sumsq ----------------------------------------------------
template<int NC>
__global__ void col_stats_k(const float* __restrict__ H, float* __restrict__ stats) {
    int c = threadIdx.x;
    int rowsPer = BATCH / gridDim.x;
    int r0 = blockIdx.x * rowsPer;
    float s = 0.f, sq = 0.f;
    for (int r = r0; r < r0 + rowsPer; ++r) {
        float v = H[(size_t)r * NC + c];
        s += v; sq += v * v;
    }
    atomicAdd(&stats[c], s);
    atomicAdd(&stats[NC + c], sq);
}

__global__ void bn_prep_k(const float* __restrict__ g, const float* __restrict__ be) {
    int c = threadIdx.x;
    float s  = g_stats1[c];
    float sq = g_stats1[H1N + c];
    float mean = s * (1.f / BATCH);
    float var  = sq * (1.f / BATCH) - mean * mean;
    float rstd = rsqrtf(var + BN_EPS);
    float scl  = g[c] * rstd;
    g_sc1[c] = scl;
    g_sh1[c] = be[c] - mean * scl;
}

// relu(BN(H1)) -> bf16 hi/lo
__global__ void act_k() {
    int q = blockIdx.x * blockDim.x + threadIdx.x;
    float4 v = ((const float4*)g_H1)[q];
    int c = (q * 4) & (H1N - 1);
    float h0 = fmaxf(fmaf(v.x, g_sc1[c + 0], g_sh1[c + 0]), 0.f);
    float h1 = fmaxf(fmaf(v.y, g_sc1[c + 1], g_sh1[c + 1]), 0.f);
    float h2 = fmaxf(fmaf(v.z, g_sc1[c + 2], g_sh1[c + 2]), 0.f);
    float h3 = fmaxf(fmaf(v.w, g_sc1[c + 3], g_sh1[c + 3]), 0.f);
    __nv_bfloat162 a = __floats2bfloat162_rn(h0, h1);
    __nv_bfloat162 b = __floats2bfloat162_rn(h2, h3);
    float l0 = h0 - __bfloat162float(a.x), l1 = h1 - __bfloat162float(a.y);
    float l2 = h2 - __bfloat162float(b.x), l3 = h3 - __bfloat162float(b.y);
    __nv_bfloat162 la = __floats2bfloat162_rn(l0, l1);
    __nv_bfloat162 lb = __floats2bfloat162_rn(l2, l3);
    uint2 uh = {*(uint32_t*)&a, *(uint32_t*)&b};
    uint2 ul = {*(uint32_t*)&la, *(uint32_t*)&lb};
    ((uint2*)g_A2h)[q] = uh;
    ((uint2*)g_A2l)[q] = ul;
}

// out = fm + relu(BN(H2)) @ W3 + b3
__global__ void final_k(const float* __restrict__ W3, const float* __restrict__ b3,
                        const float* __restrict__ g2, const float* __restrict__ be2,
                        float* __restrict__ out) {
    __shared__ float sc[H2N], sh[H2N], w3s[H2N];
    int tid = threadIdx.x;
    if (tid < H2N) {
        float s  = g_stats2[tid];
        float sq = g_stats2[H2N + tid];
        float mean = s * (1.f / BATCH);
        float var  = sq * (1.f / BATCH) - mean * mean;
        float rstd = rsqrtf(var + BN_EPS);
        float scl  = g2[tid] * rstd;
        sc[tid] = scl;
        sh[tid] = be2[tid] - mean * scl;
        w3s[tid] = W3[tid];
    }
    __syncthreads();
    int warp = tid >> 5, lane = tid & 31;
    int row = blockIdx.x * 8 + warp;
    float acc = 0.f;
#pragma unroll
    for (int j = 0; j < 4; ++j) {
        int c = lane + j * 32;
        float v = g_H2[(size_t)row * H2N + c];
        acc += fmaxf(fmaf(v, sc[c], sh[c]), 0.f) * w3s[c];
    }
#pragma unroll
    for (int o = 16; o; o >>= 1) acc += __shfl_xor_sync(0xffffffffu, acc, o);
    if (lane == 0) out[row] = g_fm[row] + acc + b3[0];
}

// ---------------------------------------------------------------------------
extern "C" void kernel_launch(void* const* d_in, const int* in_sizes, int n_in,
                              void* d_out, int out_size) {
    const int*   xc   = (const int*)  d_in[0];
    const float* lin  = (const float*)d_in[1];
    const float* lat  = (const float*)d_in[2];
    const float* W1   = (const float*)d_in[3];
    const float* b1   = (const float*)d_in[4];
    const float* g1   = (const float*)d_in[5];
    const float* be1  = (const float*)d_in[6];
    const float* W2   = (const float*)d_in[7];
    const float* b2   = (const float*)d_in[8];
    const float* g2   = (const float*)d_in[9];
    const float* be2  = (const float*)d_in[10];
    const float* W3   = (const float*)d_in[11];
    const float* b3   = (const float*)d_in[12];
    const float* bias = (const float*)d_in[13];
    float* out = (float*)d_out;

    unsigned short *pXh, *pXl, *pA2h, *pA2l, *pW1h, *pW1l, *pW2h, *pW2l;
    float *pH1, *pH2, *pS1, *pS2;
    cudaGetSymbolAddress((void**)&pXh,  g_Xh);
    cudaGetSymbolAddress((void**)&pXl,  g_Xl);
    cudaGetSymbolAddress((void**)&pA2h, g_A2h);
    cudaGetSymbolAddress((void**)&pA2l, g_A2l);
    cudaGetSymbolAddress((void**)&pW1h, g_W1Th);
    cudaGetSymbolAddress((void**)&pW1l, g_W1Tl);
    cudaGetSymbolAddress((void**)&pW2h, g_W2Th);
    cudaGetSymbolAddress((void**)&pW2l, g_W2Tl);
    cudaGetSymbolAddress((void**)&pH1,  g_H1);
    cudaGetSymbolAddress((void**)&pH2,  g_H2);
    cudaGetSymbolAddress((void**)&pS1,  g_stats1);
    cudaGetSymbolAddress((void**)&pS2,  g_stats2);

    constexpr int SMEM = 4 * 128 * 72 * 2;  // 73728 bytes
    cudaFuncSetAttribute(gemm_mma<DIN, H1N>,
                         cudaFuncAttributeMaxDynamicSharedMemorySize, SMEM);
    cudaFuncSetAttribute(gemm_mma<H1N, H2N>,
                         cudaFuncAttributeMaxDynamicSharedMemorySize, SMEM);

    zero_stats_k<<<1, 256>>>();
    prep_w_k<<<480, 256>>>(W1, W2);
    gather_fm_k<<<BATCH / 8, 256>>>(xc, lin, lat, bias);
    gemm_mma<DIN, H1N><<<dim3(BATCH / 128, H1N / 128), 256, SMEM>>>(
        pXh, pXl, pW1h, pW1l, b1, pH1);
    col_stats_k<H1N><<<512, H1N>>>(pH1, pS1);
    bn_prep_k<<<1, H1N>>>(g1, be1);
    act_k<<<(BATCH * H1N / 4) / 256, 256>>>();
    gemm_mma<H1N, H2N><<<dim3(BATCH / 128, H2N / 128), 256, SMEM>>>(
        pA2h, pA2l, pW2h, pW2l, b2, pH2);
    col_stats_k<H2N><<<512, H2N>>>(pH2, pS2);
    final_k<<<BATCH / 8, 256>>>(W3, b3, g2, be2, out);
}